// round 17
// baseline (speedup 1.0000x reference)
#include <cuda_runtime.h>
#include <cuda_fp16.h>
#include <math.h>
#include <stdint.h>

#define NE    2048
#define FEAT  512
#define REST  8
#define HEAD  8
#define HL    512
#define NCOL  16384
#define OUTC  (HEAD*512)
#define BKH   64
#define PADH  72
#define ASTRH (128*PADH)
#define STG   3
#define SMEM_BYTES (2 * STG * ASTRH * 2)   // 110592 bytes
#define SPAD  136
// ticket layout: [0,384) W-round | [384,2432) transpose | [2432,3968) proj
//                [3968,6016) scores | [6016,6528) combine
#define T_W    384
#define T_XT   2432
#define T_PROJ 3968
#define T_SC   6016
#define NTILE  6528

// ---------------- scratch ----------------------------------------------------
__device__ __half g_Y  [(size_t)2 * HEAD * NE * 512];
__device__ __half g_Yd [(size_t)HEAD * 512 * NE];
__device__ __half g_xt [(size_t)NCOL * FEAT];
__device__ __half g_W  [(size_t)3 * HL * FEAT];
__device__ __half g_S  [(size_t)HEAD * NE * NE];
__device__ float  g_ss [3 * NE];
__device__ float  g_rs [(size_t)HEAD * NE];
__device__ int    g_wc [4];      // W-round completion per p (target 128)
__device__ int    g_xc [16];     // transpose completion per e-block (target 128)
__device__ int    g_ec [16];     // proj completion per e-block (target 96)
__device__ int    g_hc [8];      // scores completion per head (target 256)
__device__ int    g_ticket;

// ---------------- helpers ----------------------------------------------------
__device__ __forceinline__ uint32_t smem_u32(const void* p) {
    uint32_t a;
    asm("{ .reg .u64 t; cvta.to.shared.u64 t, %1; cvt.u32.u64 %0, t; }" : "=r"(a) : "l"(p));
    return a;
}
__device__ __forceinline__ void mma16(float* c, const uint32_t* a, const uint32_t* b) {
    asm volatile(
        "mma.sync.aligned.m16n8k16.row.col.f32.f16.f16.f32 "
        "{%0,%1,%2,%3}, {%4,%5,%6,%7}, {%8,%9}, {%0,%1,%2,%3};"
        : "+f"(c[0]), "+f"(c[1]), "+f"(c[2]), "+f"(c[3])
        : "r"(a[0]), "r"(a[1]), "r"(a[2]), "r"(a[3]), "r"(b[0]), "r"(b[1]));
}
__device__ __forceinline__ void ldsm4(uint32_t* r, uint32_t addr) {
    asm volatile("ldmatrix.sync.aligned.m8n8.x4.shared.b16 {%0,%1,%2,%3}, [%4];"
                 : "=r"(r[0]), "=r"(r[1]), "=r"(r[2]), "=r"(r[3]) : "r"(addr));
}
__device__ __forceinline__ void cp16(uint32_t dst, const void* src) {
    uint64_t g;
    asm("cvta.to.global.u64 %0, %1;" : "=l"(g) : "l"(src));
    asm volatile("cp.async.cg.shared.global [%0], [%1], 16;" :: "r"(dst), "l"(g));
}
__device__ __forceinline__ void wait_cnt(int* p, int target) {
    if (threadIdx.x == 0) {
        while (*(volatile int*)p < target) __nanosleep(128);
    }
    __syncthreads();
}
__device__ __forceinline__ void mark_done(int* p) {
    __syncthreads();
    if (threadIdx.x == 0) {
        __threadfence();
        atomicAdd(p, 1);
    }
}

__device__ __forceinline__ void ld_k(__half* S, const __half* gp, int ldk, int k0, int tid) {
#pragma unroll
    for (int i = 0; i < 8; i++) {
        int idx = tid + i * 128;
        int row = idx >> 3, ch = idx & 7;
        cp16(smem_u32(S + row * PADH + ch * 8), gp + (size_t)row * ldk + k0 + ch * 8);
    }
}

struct Acc { float a[4][8][4]; };

// ---------------- 3-stage, BK=64, fragment double-buffered mainloop ----------
__device__ __forceinline__ void gemm_main(Acc& F, const __half* A, const __half* B,
                                          int K, __half* sA, __half* sB) {
    const int tid = threadIdx.x;
    const int lane = tid & 31, wid = tid >> 5;
    const int wm = (wid & 1) * 64, wn = (wid >> 1) * 64;

    const int offA = (wm + (lane & 7) + ((lane >> 3) & 1) * 8) * PADH + ((lane >> 4) & 1) * 8;
    const int offB = (wn + (lane & 7) + ((lane >> 4) & 1) * 8) * PADH + ((lane >> 3) & 1) * 8;

    const uint32_t sA0 = smem_u32(sA), sB0 = smem_u32(sB);

#pragma unroll
    for (int mt = 0; mt < 4; mt++)
#pragma unroll
        for (int nt = 0; nt < 8; nt++)
#pragma unroll
            for (int j = 0; j < 4; j++) F.a[mt][nt][j] = 0.f;

#pragma unroll
    for (int s = 0; s < STG - 1; s++) {
        ld_k(sA + s * ASTRH, A, K, s * BKH, tid);
        ld_k(sB + s * ASTRH, B, K, s * BKH, tid);
        asm volatile("cp.async.commit_group;" ::: "memory");
    }

    const int KT = K / BKH;
    int ls = STG - 1;
    for (int kt = 0; kt < KT; kt++) {
        asm volatile("cp.async.wait_group %0;" :: "n"(STG - 2) : "memory");
        __syncthreads();
        if (kt + STG - 1 < KT) {
            ld_k(sA + ls * ASTRH, A, K, (kt + STG - 1) * BKH, tid);
            ld_k(sB + ls * ASTRH, B, K, (kt + STG - 1) * BKH, tid);
            ls = (ls + 1 == STG) ? 0 : ls + 1;
        }
        asm volatile("cp.async.commit_group;" ::: "memory");

        int buf = kt % STG;
        const uint32_t aB = sA0 + (buf * ASTRH + offA) * 2;
        const uint32_t bB = sB0 + (buf * ASTRH + offB) * 2;

        uint32_t af[2][4][4], bf[2][4][4];
#pragma unroll
        for (int mt = 0; mt < 4; mt++) ldsm4(af[0][mt], aB + (mt * 16 * PADH) * 2);
#pragma unroll
        for (int np = 0; np < 4; np++) ldsm4(bf[0][np], bB + (np * 16 * PADH) * 2);

#pragma unroll
        for (int ks = 0; ks < 4; ks++) {
            int cur = ks & 1, nxt = cur ^ 1;
            if (ks < 3) {
#pragma unroll
                for (int mt = 0; mt < 4; mt++)
                    ldsm4(af[nxt][mt], aB + (mt * 16 * PADH + 16 * (ks + 1)) * 2);
#pragma unroll
                for (int np = 0; np < 4; np++)
                    ldsm4(bf[nxt][np], bB + (np * 16 * PADH + 16 * (ks + 1)) * 2);
            }
#pragma unroll
            for (int mt = 0; mt < 4; mt++)
#pragma unroll
                for (int np = 0; np < 4; np++) {
                    mma16(F.a[mt][2 * np + 0], af[cur][mt], &bf[cur][np][0]);
                    mma16(F.a[mt][2 * np + 1], af[cur][mt], &bf[cur][np][2]);
                }
        }
    }
    __syncthreads();
}

// ---------------- init: zero counters + accumulators -------------------------
__global__ __launch_bounds__(256) void init_k() {
    int i = blockIdx.x * 256 + threadIdx.x;
    if (i < 3 * NE) g_ss[i] = 0.f;
    if (i < HEAD * NE) g_rs[i] = 0.f;
    if (i < 4)  g_wc[i] = 0;
    if (i >= 4 && i < 20)  g_xc[i - 4] = 0;
    if (i >= 20 && i < 36) g_ec[i - 20] = 0;
    if (i >= 36 && i < 44) g_hc[i - 36] = 0;
    if (i == 44) g_ticket = 0;
}

// ---------------- tile bodies ------------------------------------------------
__device__ __forceinline__ void w_tile(int t, const float* Wq, const float* Wk,
                                       const float* Wd) {
    int p = t >> 7;                       // 128 tiles per p
    int base = (t & 127) * 2048;          // floats within p
    const float* W = (p == 0) ? Wq : (p == 1) ? Wk : Wd;
#pragma unroll
    for (int i = 0; i < 4; i++) {
        int off = base + (threadIdx.x + i * 128) * 4;
        float4 v = *(const float4*)(W + off);
        size_t d = (size_t)p * 262144 + off;
        *(__half2*)(g_W + d)     = make_half2(__float2half_rn(v.x), __float2half_rn(v.y));
        *(__half2*)(g_W + d + 2) = make_half2(__float2half_rn(v.z), __float2half_rn(v.w));
    }
    mark_done(&g_wc[p]);
}

__device__ __forceinline__ void xt_tile(int n, const float* x, float* s) {
    const int tid = threadIdx.x;
    const float* src = x + (size_t)n * 4096;
#pragma unroll
    for (int j = 0; j < 8; j++) {
        int v = (tid + j * 128) * 4;
        float4 t = *(const float4*)(src + v);
        int f = v >> 3, rr = v & 7;
        s[f * 9 + rr + 0] = t.x; s[f * 9 + rr + 1] = t.y;
        s[f * 9 + rr + 2] = t.z; s[f * 9 + rr + 3] = t.w;
    }
    __syncthreads();
#pragma unroll
    for (int rr = 0; rr < 8; rr++) {
        int f = tid * 4;
        __half2 a = make_half2(__float2half_rn(s[f * 9 + rr]),
                               __float2half_rn(s[(f + 1) * 9 + rr]));
        __half2 b = make_half2(__float2half_rn(s[(f + 2) * 9 + rr]),
                               __float2half_rn(s[(f + 3) * 9 + rr]));
        __half* d = g_xt + ((size_t)n * 8 + rr) * 512 + f;
        *(__half2*)d = a; *(__half2*)(d + 2) = b;
    }
    mark_done(&g_xc[n >> 7]);
}

__device__ __forceinline__ void proj_tile(int e, int p, int m0, int c0,
                                          __half* sA, __half* sB, float* red) {
    const int tid = threadIdx.x, lane = tid & 31, wid = tid >> 5;
    const int g8 = lane >> 2, tg = lane & 3;
    const int wm = (wid & 1) * 64, wn = (wid >> 1) * 64;

    wait_cnt(&g_wc[p], 128);
    wait_cnt(&g_xc[e], 128);

    red[tid] = 0.f;

    Acc F;
    gemm_main(F, g_W + (size_t)p * HL * FEAT + (size_t)m0 * FEAT,
              g_xt + (size_t)c0 * FEAT, FEAT, sA, sB);

    float sq[8];
#pragma unroll
    for (int nt = 0; nt < 8; nt++) sq[nt] = 0.f;

    if (p < 2) {
        __half* base = g_Y + (size_t)p * HEAD * NE * 512;
#pragma unroll
        for (int mt = 0; mt < 4; mt++)
#pragma unroll
            for (int half = 0; half < 2; half++) {
                int row = m0 + wm + mt * 16 + g8 + half * 8;
                int hh = row >> 6, l = row & 63;
#pragma unroll
                for (int nt = 0; nt < 8; nt++) {
                    int col = c0 + wn + nt * 8 + 2 * tg;
                    int n = col >> 3, r = col & 7;
                    __half h0 = __float2half_rn(F.a[mt][nt][half * 2 + 0]);
                    __half h1 = __float2half_rn(F.a[mt][nt][half * 2 + 1]);
                    float v0 = __half2float(h0), v1 = __half2float(h1);
                    *(__half2*)(base + ((size_t)hh * NE + n) * 512 + l * 8 + r) = make_half2(h0, h1);
                    sq[nt] += v0 * v0 + v1 * v1;
                }
            }
    } else {
        __half* sSt = sA;
#pragma unroll
        for (int mt = 0; mt < 4; mt++)
#pragma unroll
            for (int half = 0; half < 2; half++) {
                int srow = wm + mt * 16 + g8 + half * 8;
#pragma unroll
                for (int nt = 0; nt < 8; nt++) {
                    int scol = wn + nt * 8 + 2 * tg;
                    __half h0 = __float2half_rn(F.a[mt][nt][half * 2 + 0]);
                    __half h1 = __float2half_rn(F.a[mt][nt][half * 2 + 1]);
                    float v0 = __half2float(h0), v1 = __half2float(h1);
                    sq[nt] += v0 * v0 + v1 * v1;
                    *(__half2*)(sSt + srow * SPAD + scol) = make_half2(h0, h1);
                }
            }
        __syncthreads();
        {
            int i = tid;
            int rowg = m0 + i, hh = rowg >> 6, l = rowg & 63;
            int mb0 = c0 >> 3;
#pragma unroll
            for (int rp = 0; rp < 4; rp++) {
                __half ra[16], rb[16];
#pragma unroll
                for (int m = 0; m < 16; m++) {
                    __half2 u = *(__half2*)(sSt + i * SPAD + m * 8 + 2 * rp);
                    ra[m] = u.x; rb[m] = u.y;
                }
                __half* d0 = g_Yd + ((size_t)hh * 512 + l * 8 + 2 * rp) * NE + mb0;
                __half* d1 = d0 + NE;
                *(uint4*)d0 = *(uint4*)ra;  *(uint4*)(d0 + 8) = *(uint4*)(ra + 8);
                *(uint4*)d1 = *(uint4*)rb;  *(uint4*)(d1 + 8) = *(uint4*)(rb + 8);
            }
        }
        __syncthreads();
    }
#pragma unroll
    for (int nt = 0; nt < 8; nt++) {
        float v = sq[nt];
        v += __shfl_down_sync(0xffffffffu, v, 4);
        v += __shfl_down_sync(0xffffffffu, v, 8);
        v += __shfl_down_sync(0xffffffffu, v, 16);
        if (g8 == 0) atomicAdd(&red[wn + nt * 8 + 2 * tg], v);
    }
    __syncthreads();
    if (tid < 16) {
        float s = 0.f;
#pragma unroll
        for (int j = 0; j < 8; j += 2) s += red[tid * 8 + j];
        atomicAdd(&g_ss[p * NE + (c0 >> 3) + tid], s);
    }
    mark_done(&g_ec[e]);
}

__device__ __forceinline__ void scores_tile(int h, int m0, int n0,
                                            __half* sA, __half* sB, float* red) {
    const int tid = threadIdx.x, lane = tid & 31, wid = tid >> 5;
    const int g8 = lane >> 2, tg = lane & 3;
    const int wm = (wid & 1) * 64, wn = (wid >> 1) * 64;

    wait_cnt(&g_ec[m0 >> 7], 96);
    wait_cnt(&g_ec[n0 >> 7], 96);

    red[tid] = 0.f;

    Acc F;
    gemm_main(F, g_Y + ((size_t)h * NE + m0) * 512,
              g_Y + (((size_t)HEAD + h) * NE + n0) * 512, 512, sA, sB);

    float rk[8][2], rd[8][2];
#pragma unroll
    for (int nt = 0; nt < 8; nt++) {
        int col = n0 + wn + nt * 8 + 2 * tg;
        rk[nt][0] = rsqrtf(g_ss[NE + col]);     rk[nt][1] = rsqrtf(g_ss[NE + col + 1]);
        rd[nt][0] = rsqrtf(g_ss[2 * NE + col]); rd[nt][1] = rsqrtf(g_ss[2 * NE + col + 1]);
    }

    __half* sSt = sA;
#pragma unroll
    for (int mt = 0; mt < 4; mt++)
#pragma unroll
        for (int half = 0; half < 2; half++) {
            int srow = wm + mt * 16 + g8 + half * 8;
            float rq = rsqrtf(g_ss[m0 + srow]);
            float rs = 0.f;
#pragma unroll
            for (int nt = 0; nt < 8; nt++) {
                int scol = wn + nt * 8 + 2 * tg;
                float e0 = __expf(F.a[mt][nt][half * 2 + 0] * rq * rk[nt][0]);
                float e1 = __expf(F.a[mt][nt][half * 2 + 1] * rq * rk[nt][1]);
                rs += e0 + e1;
                __half2 ph = make_half2(__float2half_rn(e0 * rd[nt][0]),
                                        __float2half_rn(e1 * rd[nt][1]));
                *(__half2*)(sSt + srow * SPAD + scol) = ph;
            }
            rs += __shfl_down_sync(0xffffffffu, rs, 1);
            rs += __shfl_down_sync(0xffffffffu, rs, 2);
            if (tg == 0) atomicAdd(&red[wm + mt * 16 + g8 + half * 8], rs);
        }
    __syncthreads();

    {
        const size_t rowg = (size_t)h * NE + m0;
#pragma unroll
        for (int it = 0; it < 32; it++) {
            int row = it * 4 + wid;
            uint2 v = *(uint2*)(sSt + row * SPAD + lane * 4);
            *(uint2*)(g_S + (rowg + row) * NE + n0 + lane * 4) = v;
        }
    }
    atomicAdd(&g_rs[(size_t)h * NE + m0 + tid], red[tid]);
    mark_done(&g_hc[h]);
}

__device__ __forceinline__ void combine_tile(int h, int m0, int lr0,
                                             __half* sA, __half* sB, float* out) {
    const int tid = threadIdx.x, lane = tid & 31, wid = tid >> 5;
    const int g8 = lane >> 2, tg = lane & 3;
    const int wm = (wid & 1) * 64, wn = (wid >> 1) * 64;

    wait_cnt(&g_hc[h], 256);

    Acc F;
    gemm_main(F, g_S + ((size_t)h * NE + m0) * NE,
              g_Yd + ((size_t)h * 512 + lr0) * NE, NE, sA, sB);

#pragma unroll
    for (int mt = 0; mt < 4; mt++)
#pragma unroll
        for (int half = 0; half < 2; half++) {
            int row = m0 + wm + mt * 16 + g8 + half * 8;
            float inv = 1.0f / g_rs[(size_t)h * NE + row];
#pragma unroll
            for (int nt = 0; nt < 8; nt++) {
                int col = lr0 + wn + nt * 8 + 2 * tg;
                float v0 = F.a[mt][nt][half * 2 + 0] * inv;
                float v1 = F.a[mt][nt][half * 2 + 1] * inv;
                *(float2*)(out + (size_t)row * OUTC + h * 512 + col) = make_float2(v0, v1);
            }
        }
}

// ---------------- persistent main kernel -------------------------------------
__global__ __launch_bounds__(128) void main_tc(float* __restrict__ out,
                                               const float* __restrict__ x,
                                               const float* __restrict__ Wq,
                                               const float* __restrict__ Wk,
                                               const float* __restrict__ Wd) {
    extern __shared__ __half dsm[];
    __shared__ int s_tile;
    __shared__ float red[128];
    __half* sA = dsm;
    __half* sB = dsm + STG * ASTRH;
    const int tid = threadIdx.x;

    for (;;) {
        __syncthreads();
        if (tid == 0) s_tile = atomicAdd(&g_ticket, 1);
        __syncthreads();
        int idx = s_tile;
        if (idx >= NTILE) return;

        if (idx < T_W) {
            w_tile(idx, Wq, Wk, Wd);
        } else if (idx < T_XT) {
            xt_tile(idx - T_W, x, (float*)dsm);
        } else if (idx < T_PROJ) {
            int t = idx - T_XT;
            int e = t / 96, r = t % 96;
            int p = r >> 5, r2 = r & 31;
            int m0 = (r2 >> 3) * 128;
            int c0 = (e * 8 + (r2 & 7)) * 128;
            proj_tile(e, p, m0, c0, sA, sB, red);
        } else if (idx < T_SC) {
            int s = idx - T_PROJ;
            int h = s >> 8, i = (s >> 4) & 15, j = s & 15;
            scores_tile(h, i * 128, j * 128, sA, sB, red);
        } else {
            int c = idx - T_SC;
            int h = c >> 6, r = c & 63;
            combine_tile(h, (r >> 2) * 128, (r & 3) * 128, sA, sB, out);
        }
    }
}

// ---------------------------------------------------------------------------
extern "C" void kernel_launch(void* const* d_in, const int* in_sizes, int n_in,
                              void* d_out, int out_size) {
    const float* x  = (const float*)d_in[0];
    const float* Wq = (const float*)d_in[1];
    const float* Wk = (const float*)d_in[2];
    const float* Wd = (const float*)d_in[3];
    float* out = (float*)d_out;

    cudaFuncSetAttribute(main_tc, cudaFuncAttributeMaxDynamicSharedMemorySize, SMEM_BYTES);

    init_k<<<88, 256>>>();
    main_tc<<<296, 128, SMEM_BYTES>>>(out, x, Wq, Wk, Wd);
}